// round 17
// baseline (speedup 1.0000x reference)
#include <cuda_runtime.h>
#include <cuda_fp16.h>

// ---------------------------------------------------------------------------
// Problem constants
// ---------------------------------------------------------------------------
#define BATCH 1024
#define DIN   512
#define DH    1024
#define DOUT  512
#define MHIST 6
#define MAXIT 40
#define LAM   1e-4f

#define SZ (BATCH * DH)

// ---------------------------------------------------------------------------
// Scratch (device globals: no runtime allocation allowed)
// ---------------------------------------------------------------------------
__device__ float g_z[SZ];                  // current iterate xk (fp32)
__device__ __half g_F16[MHIST * SZ];       // F history (fp16)
__device__ __half g_G16[MHIST * SZ];       // residuals G = F - X (fp16)
// fp16 activation operands
__device__ __half g_xf16[BATCH * DIN];
__device__ __half g_Af16[SZ];              // current z-like operand
__device__ __half g_Hf16[SZ];              // hidden activations
// fp16 weights, transposed to [N,K] K-major
__device__ __half g_W1T[DH * DH];
__device__ __half g_W2T[DH * DH];
__device__ __half g_WinT[DIN * DH];        // [1024 N, 512 K]
__device__ __half g_WoutT[DH * DOUT];      // [512 N, 1024 K]

// ---------------------------------------------------------------------------
// Helpers
// ---------------------------------------------------------------------------
__device__ __forceinline__ unsigned smem_u32(const void* p) {
    unsigned r;
    asm("{ .reg .u64 t; cvta.to.shared.u64 t, %1; cvt.u32.u64 %0, t; }"
        : "=r"(r) : "l"(p));
    return r;
}

__device__ __forceinline__ unsigned pack_half2(float x, float y) {
    __half2 h = __floats2half2_rn(x, y);
    return *reinterpret_cast<unsigned*>(&h);
}

#define LDSM4(r, addr) \
    asm volatile("ldmatrix.sync.aligned.m8n8.x4.shared.b16 {%0,%1,%2,%3}, [%4];" \
        : "=r"((r)[0]), "=r"((r)[1]), "=r"((r)[2]), "=r"((r)[3]) : "r"(addr))
#define MMA_F16(d, a, b0, b1) \
    asm volatile("mma.sync.aligned.m16n8k16.row.col.f32.f16.f16.f32 " \
        "{%0,%1,%2,%3}, {%4,%5,%6,%7}, {%8,%9}, {%0,%1,%2,%3};" \
        : "+f"((d)[0]), "+f"((d)[1]), "+f"((d)[2]), "+f"((d)[3]) \
        : "r"((a)[0]), "r"((a)[1]), "r"((a)[2]), "r"((a)[3]), \
          "r"(b0), "r"(b1))

#define CP_ASYNC16(dst, src) \
    asm volatile("cp.async.cg.shared.global [%0], [%1], 16;" \
        :: "r"(dst), "l"(src) : "memory")
#define CP_COMMIT() asm volatile("cp.async.commit_group;" ::: "memory")
#define CP_WAIT2()  asm volatile("cp.async.wait_group 2;"  ::: "memory")

// ---------------------------------------------------------------------------
// Weight transpose to fp16: W[Kd,Nd] fp32 -> WT[Nd,Kd] fp16
// ---------------------------------------------------------------------------
__global__ void __launch_bounds__(256)
trans_kernel(const float* __restrict__ W, __half* __restrict__ WT,
             int Kd, int Nd)
{
    __shared__ float tile[32][33];
    const int tx = threadIdx.x & 31, ty = threadIdx.x >> 5;
    const int kb = blockIdx.y * 32, nb = blockIdx.x * 32;
#pragma unroll
    for (int r = 0; r < 4; ++r)
        tile[ty + r * 8][tx] = W[(size_t)(kb + ty + r * 8) * Nd + nb + tx];
    __syncthreads();
#pragma unroll
    for (int r = 0; r < 4; ++r) {
        const int n = ty + r * 8;
        WT[(size_t)(nb + n) * Kd + kb + tx] = __float2half_rn(tile[tx][n]);
    }
}

// fp32 -> fp16 convert (vectorized)
__global__ void __launch_bounds__(256)
tof16_kernel(const float* __restrict__ src, __half* __restrict__ dst)
{
    const size_t i = ((size_t)blockIdx.x * 256 + threadIdx.x) * 4;
    float4 v = *reinterpret_cast<const float4*>(src + i);
    uint2 o;
    o.x = pack_half2(v.x, v.y);
    o.y = pack_half2(v.z, v.w);
    *reinterpret_cast<uint2*>(dst + i) = o;
}

// ---------------------------------------------------------------------------
// fp16 GEMM with in-CTA k-split:  D = A*B + bias, fp32 accum.
// A[M,K] K-major fp16, B[N,K] K-major fp16 (pre-transposed weights).
// CTA tile 128x64, KT=64; 8 warps as 2(m) x 2(n) x 2(k); warp tile 64x32.
// Epilogue (warp_k==0 warps) writes any of:
//   C    : fp32 result
//   G16o : fp16 residual v - zin   (zin read BEFORE any zout write)
//   F16o : fp16 result
//   zout : fp32 result
//   S    : fp16 result (next GEMM operand)
// ---------------------------------------------------------------------------
#define STAGE_B 24576
#define NSTAGES 4
#define SMEM_MMA (NSTAGES * STAGE_B + 32768)

template <bool RELU, int K, int N>
__global__ void __launch_bounds__(256, 1)
gemm_mma(const __half* __restrict__ A,
         const __half* __restrict__ B,
         const float* __restrict__ bias,
         float* __restrict__ C,
         const float* __restrict__ zin,
         __half* __restrict__ F16o,
         __half* __restrict__ G16o,
         float* __restrict__ zout,
         __half* __restrict__ S)
{
    constexpr int KT = 64, T = K / KT;
    extern __shared__ char smem[];
    const unsigned sbase = smem_u32(smem);
    float* const red = reinterpret_cast<float*>(smem + NSTAGES * STAGE_B);
    const int tid = threadIdx.x;
    const int lane = tid & 31, wid = tid >> 5;
    const int warp_m = wid >> 2;         // 0..1 (64-row half)
    const int warp_n = (wid >> 1) & 1;   // 0..1 (32-col half)
    const int warp_k = wid & 1;          // 0..1 (k-step half)
    const int m0 = blockIdx.y * 128, n0 = blockIdx.x * 64;

    float acc[4][4][4];
#pragma unroll
    for (int i = 0; i < 4; ++i)
#pragma unroll
        for (int j = 0; j < 4; ++j)
#pragma unroll
            for (int c = 0; c < 4; ++c) acc[i][j][c] = 0.f;

    const int lrow = tid >> 3;
    const int lc16 = tid & 7;

    auto load_stage = [&](int t, int s) {
        const int kt = t * KT;
        const unsigned stb = sbase + s * STAGE_B;
        const unsigned off0 = lrow * 128 + lc16 * 16;
        const unsigned sw0 = off0 ^ ((off0 >> 3) & 0x70);
#pragma unroll
        for (int it = 0; it < 4; ++it) {
            const size_t goff = (size_t)(m0 + it * 32 + lrow) * K + kt + lc16 * 8;
            CP_ASYNC16(stb + it * 4096 + sw0, A + goff);
        }
#pragma unroll
        for (int it = 0; it < 2; ++it) {
            const size_t goff = (size_t)(n0 + it * 32 + lrow) * K + kt + lc16 * 8;
            CP_ASYNC16(stb + 16384 + it * 4096 + sw0, B + goff);
        }
    };

    const int lr8 = lane & 7;
    const int lg  = (lane >> 3) & 1;
    const int lcg = lane >> 4;
    unsigned aoff[4];
#pragma unroll
    for (int i = 0; i < 4; ++i)
        aoff[i] = (unsigned)(warp_m * 64 + i * 16 + lr8 + lg * 8) * 128 + lcg * 16;
    unsigned boff[2];
#pragma unroll
    for (int jj = 0; jj < 2; ++jj)
        boff[jj] = (unsigned)(warp_n * 32 + jj * 16 + lr8 + lcg * 8) * 128 + lg * 16;

    unsigned af0[4][4], bf0[2][4], af1[4][4], bf1[2][4];

    auto ldA = [&](unsigned (&af)[4][4], unsigned st, int ks) {
#pragma unroll
        for (int i = 0; i < 4; ++i) {
            unsigned off = aoff[i] + ks * 32;
            unsigned sw = off ^ ((off >> 3) & 0x70);
            LDSM4(af[i], st + sw);
        }
    };
    auto ldB = [&](unsigned (&bf)[2][4], unsigned st, int ks) {
#pragma unroll
        for (int jj = 0; jj < 2; ++jj) {
            unsigned off = boff[jj] + ks * 32;
            unsigned sw = off ^ ((off >> 3) & 0x70);
            LDSM4(bf[jj], st + 16384 + sw);
        }
    };
    auto domma = [&](unsigned (&af)[4][4], unsigned (&bf)[2][4]) {
#pragma unroll
        for (int i = 0; i < 4; ++i)
#pragma unroll
            for (int j = 0; j < 4; ++j) {
                const int jj = j >> 1, p = (j & 1) * 2;
                MMA_F16(acc[i][j], af[i], bf[jj][p], bf[jj][p + 1]);
            }
    };

#pragma unroll
    for (int s = 0; s < NSTAGES - 1; ++s) {
        load_stage(s, s);
        CP_COMMIT();
    }
    const int ks_a = warp_k * 2, ks_b = ks_a + 1;
    for (int t = 0; t < T; ++t) {
        CP_WAIT2();
        __syncthreads();
        if (t + NSTAGES - 1 < T)
            load_stage(t + NSTAGES - 1, (t + NSTAGES - 1) & (NSTAGES - 1));
        CP_COMMIT();
        const unsigned st = sbase + (t & (NSTAGES - 1)) * STAGE_B;
        ldA(af0, st, ks_a); ldB(bf0, st, ks_a);
        ldA(af1, st, ks_b); ldB(bf1, st, ks_b);
        domma(af0, bf0);
        domma(af1, bf1);
    }

    // ---- k-reduction through smem ----
    const int erow = lane >> 2;
    const int ecol = (lane & 3) * 2;
    if (warp_k == 1) {
#pragma unroll
        for (int i = 0; i < 4; ++i) {
            const int rr = warp_m * 64 + i * 16 + erow;
#pragma unroll
            for (int j = 0; j < 4; ++j) {
                const int rc = warp_n * 32 + j * 8 + ecol;
                *reinterpret_cast<float2*>(red + rr * 64 + rc) =
                    make_float2(acc[i][j][0], acc[i][j][1]);
                *reinterpret_cast<float2*>(red + (rr + 8) * 64 + rc) =
                    make_float2(acc[i][j][2], acc[i][j][3]);
            }
        }
    }
    __syncthreads();

    // ---- epilogue by warp_k==0 warps ----
    if (warp_k == 0) {
#pragma unroll
        for (int i = 0; i < 4; ++i) {
            const int rr = warp_m * 64 + i * 16 + erow;
            const int gm = m0 + rr;
#pragma unroll
            for (int j = 0; j < 4; ++j) {
                const int rc = warp_n * 32 + j * 8 + ecol;
                const int gn = n0 + rc;
                float2 r0 = *reinterpret_cast<float2*>(red + rr * 64 + rc);
                float2 r1 = *reinterpret_cast<float2*>(red + (rr + 8) * 64 + rc);
                float2 b2 = *reinterpret_cast<const float2*>(bias + gn);
                float2 v0, v1;
                v0.x = acc[i][j][0] + r0.x + b2.x;
                v0.y = acc[i][j][1] + r0.y + b2.y;
                v1.x = acc[i][j][2] + r1.x + b2.x;
                v1.y = acc[i][j][3] + r1.y + b2.y;
                if (RELU) {
                    v0.x = fmaxf(v0.x, 0.f); v0.y = fmaxf(v0.y, 0.f);
                    v1.x = fmaxf(v1.x, 0.f); v1.y = fmaxf(v1.y, 0.f);
                }
                const size_t o0 = (size_t)gm * N + gn;
                const size_t o1 = (size_t)(gm + 8) * N + gn;
                if (G16o) {   // read zin BEFORE any zout write (may alias)
                    float2 z0 = *reinterpret_cast<const float2*>(zin + o0);
                    float2 z1 = *reinterpret_cast<const float2*>(zin + o1);
                    *reinterpret_cast<unsigned*>(G16o + o0) =
                        pack_half2(v0.x - z0.x, v0.y - z0.y);
                    *reinterpret_cast<unsigned*>(G16o + o1) =
                        pack_half2(v1.x - z1.x, v1.y - z1.y);
                }
                if (C) {
                    *reinterpret_cast<float2*>(C + o0) = v0;
                    *reinterpret_cast<float2*>(C + o1) = v1;
                }
                if (zout) {
                    *reinterpret_cast<float2*>(zout + o0) = v0;
                    *reinterpret_cast<float2*>(zout + o1) = v1;
                }
                if (F16o) {
                    *reinterpret_cast<unsigned*>(F16o + o0) = pack_half2(v0.x, v0.y);
                    *reinterpret_cast<unsigned*>(F16o + o1) = pack_half2(v1.x, v1.y);
                }
                if (S) {
                    *reinterpret_cast<unsigned*>(S + o0) = pack_half2(v0.x, v0.y);
                    *reinterpret_cast<unsigned*>(S + o1) = pack_half2(v1.x, v1.y);
                }
            }
        }
    }
}

// ---------------------------------------------------------------------------
// Fused Anderson alpha + mix, fp16 state. One CTA per batch row.
// Gram from G16 (fp16 residuals), solve bordered system, mix from F16,
// write xk to g_z (fp32) and g_Af16 (fp16).
// ---------------------------------------------------------------------------
template <int NV>
__global__ void __launch_bounds__(256)
anderson_mix_kernel(int slot)
{
    constexpr int NP = NV * (NV + 1) / 2;
    const int row = blockIdx.x;
    const int tid = threadIdx.x;
    const size_t base = (size_t)row * DH + tid * 4;   // 4 elements per thread

    // ---- load residual vectors (4 elements per slot) ----
    float g[NV][4];
#pragma unroll
    for (int j = 0; j < NV; ++j) {
        uint2 u = *reinterpret_cast<const uint2*>(g_G16 + (size_t)j * SZ + base);
        float2 f0 = __half22float2(*reinterpret_cast<__half2*>(&u.x));
        float2 f1 = __half22float2(*reinterpret_cast<__half2*>(&u.y));
        g[j][0] = f0.x; g[j][1] = f0.y; g[j][2] = f1.x; g[j][3] = f1.y;
    }

    float s[NP];
    {
        int p = 0;
#pragma unroll
        for (int j = 0; j < NV; ++j)
#pragma unroll
            for (int l = j; l < NV; ++l) {
                s[p] = g[j][0] * g[l][0] + g[j][1] * g[l][1]
                     + g[j][2] * g[l][2] + g[j][3] * g[l][3];
                ++p;
            }
    }

#pragma unroll
    for (int p = 0; p < NP; ++p) {
        float v = s[p];
#pragma unroll
        for (int off = 16; off > 0; off >>= 1)
            v += __shfl_down_sync(0xffffffffu, v, off);
        s[p] = v;
    }
    __shared__ float red[NP][8];
    __shared__ float al[NV];
    const int lane = tid & 31, warp = tid >> 5;
    if (lane == 0) {
#pragma unroll
        for (int p = 0; p < NP; ++p) red[p][warp] = s[p];
    }
    __syncthreads();

    if (tid == 0) {
        float GGp[NP];
#pragma unroll
        for (int p = 0; p < NP; ++p) {
            float v = 0.f;
#pragma unroll
            for (int w = 0; w < 8; ++w) v += red[p][w];
            GGp[p] = v;
        }
        float GG[NV][NV];
        {
            int p = 0;
#pragma unroll
            for (int j = 0; j < NV; ++j)
#pragma unroll
                for (int l = j; l < NV; ++l) { GG[j][l] = GGp[p]; GG[l][j] = GGp[p]; ++p; }
        }
        const int n = NV + 1;
        float Hm[MHIST + 1][MHIST + 2];
        Hm[0][0] = 0.f;
        for (int j = 0; j < NV; ++j) { Hm[0][1 + j] = 1.f; Hm[1 + j][0] = 1.f; }
        for (int j = 0; j < NV; ++j)
            for (int l = 0; l < NV; ++l)
                Hm[1 + j][1 + l] = GG[j][l] + (j == l ? LAM : 0.f);
        for (int r = 0; r < n; ++r) Hm[r][n] = (r == 0) ? 1.f : 0.f;

        for (int c = 0; c < n; ++c) {
            int piv = c; float best = fabsf(Hm[c][c]);
            for (int r = c + 1; r < n; ++r) {
                float v = fabsf(Hm[r][c]);
                if (v > best) { best = v; piv = r; }
            }
            if (piv != c)
                for (int cc = 0; cc <= n; ++cc) {
                    float tmp = Hm[c][cc]; Hm[c][cc] = Hm[piv][cc]; Hm[piv][cc] = tmp;
                }
            float inv = 1.f / Hm[c][c];
            for (int r = c + 1; r < n; ++r) {
                float fct = Hm[r][c] * inv;
                for (int cc = c; cc <= n; ++cc) Hm[r][cc] -= fct * Hm[c][cc];
            }
        }
        float xv[MHIST + 1];
        for (int r = n - 1; r >= 0; --r) {
            float a = Hm[r][n];
            for (int cc = r + 1; cc < n; ++cc) a -= Hm[r][cc] * xv[cc];
            xv[r] = a / Hm[r][r];
        }
#pragma unroll
        for (int j = 0; j < NV; ++j) al[j] = xv[1 + j];
    }
    __syncthreads();

    // ---- mix from fp16 F history ----
    float4 acc = make_float4(0.f, 0.f, 0.f, 0.f);
#pragma unroll
    for (int j = 0; j < NV; ++j) {
        const float a = al[j];
        uint2 u = *reinterpret_cast<const uint2*>(g_F16 + (size_t)j * SZ + base);
        float2 f0 = __half22float2(*reinterpret_cast<__half2*>(&u.x));
        float2 f1 = __half22float2(*reinterpret_cast<__half2*>(&u.y));
        acc.x += a * f0.x; acc.y += a * f0.y;
        acc.z += a * f1.x; acc.w += a * f1.y;
    }
    *reinterpret_cast<float4*>(&g_z[base]) = acc;
    uint2 sv;
    sv.x = pack_half2(acc.x, acc.y);
    sv.y = pack_half2(acc.z, acc.w);
    *reinterpret_cast<uint2*>(g_Af16 + base) = sv;
}

// ---------------------------------------------------------------------------
// Host orchestration
// ---------------------------------------------------------------------------
static void launch_anderson_mix(int nv, int slot)
{
    switch (nv) {
        case 2: anderson_mix_kernel<2><<<BATCH, 256>>>(slot); break;
        case 3: anderson_mix_kernel<3><<<BATCH, 256>>>(slot); break;
        case 4: anderson_mix_kernel<4><<<BATCH, 256>>>(slot); break;
        case 5: anderson_mix_kernel<5><<<BATCH, 256>>>(slot); break;
        default: anderson_mix_kernel<6><<<BATCH, 256>>>(slot); break;
    }
}

extern "C" void kernel_launch(void* const* d_in, const int* in_sizes, int n_in,
                              void* d_out, int out_size)
{
    const float* x     = (const float*)d_in[0];
    const float* W_in  = (const float*)d_in[1];
    const float* b_in  = (const float*)d_in[2];
    const float* W1    = (const float*)d_in[3];
    const float* b1    = (const float*)d_in[4];
    const float* W2    = (const float*)d_in[5];
    const float* b2    = (const float*)d_in[6];
    const float* W_out = (const float*)d_in[7];
    const float* b_out = (const float*)d_in[8];
    float* out = (float*)d_out;

    float* z;
    __half *xf16, *Af16, *Hf16, *F16, *G16, *W1T, *W2T, *WinT, *WoutT;
    cudaGetSymbolAddress((void**)&z, g_z);
    cudaGetSymbolAddress((void**)&xf16, g_xf16);
    cudaGetSymbolAddress((void**)&Af16, g_Af16);
    cudaGetSymbolAddress((void**)&Hf16, g_Hf16);
    cudaGetSymbolAddress((void**)&F16, g_F16);
    cudaGetSymbolAddress((void**)&G16, g_G16);
    cudaGetSymbolAddress((void**)&W1T, g_W1T);
    cudaGetSymbolAddress((void**)&W2T, g_W2T);
    cudaGetSymbolAddress((void**)&WinT, g_WinT);
    cudaGetSymbolAddress((void**)&WoutT, g_WoutT);

    cudaFuncSetAttribute(gemm_mma<true, 1024, 1024>,
                         cudaFuncAttributeMaxDynamicSharedMemorySize, SMEM_MMA);
    cudaFuncSetAttribute(gemm_mma<false, 1024, 1024>,
                         cudaFuncAttributeMaxDynamicSharedMemorySize, SMEM_MMA);
    cudaFuncSetAttribute(gemm_mma<false, 512, 1024>,
                         cudaFuncAttributeMaxDynamicSharedMemorySize, SMEM_MMA);
    cudaFuncSetAttribute(gemm_mma<false, 1024, 512>,
                         cudaFuncAttributeMaxDynamicSharedMemorySize, SMEM_MMA);

    // one-time weight transposes + input convert
    trans_kernel<<<dim3(32, 32), 256>>>(W1, W1T, DH, DH);
    trans_kernel<<<dim3(32, 32), 256>>>(W2, W2T, DH, DH);
    trans_kernel<<<dim3(32, 16), 256>>>(W_in, WinT, DIN, DH);
    trans_kernel<<<dim3(16, 32), 256>>>(W_out, WoutT, DH, DOUT);
    tof16_kernel<<<(BATCH * DIN) / 1024, 256>>>(x, xf16);

    const dim3 tcg(16, 8);   // N/64, M/128

    // z0 = x @ W_in + b_in -> z fp32 + Af16
    gemm_mma<false, 512, 1024><<<tcg, 256, SMEM_MMA>>>(
        xf16, WinT, b_in, nullptr, nullptr, nullptr, nullptr, z, Af16);

    // F0 = f(z0): G16[0] = F0 - z0, F16[0] = F0, z <- F0 (=X1), Af16 <- F0
    gemm_mma<true, 1024, 1024><<<tcg, 256, SMEM_MMA>>>(
        Af16, W1T, b1, nullptr, nullptr, nullptr, nullptr, nullptr, Hf16);
    gemm_mma<false, 1024, 1024><<<tcg, 256, SMEM_MMA>>>(
        Hf16, W2T, b2, nullptr, z, F16, G16, z, Af16);
    // F1 = f(F0): G16[1] = F1 - F0, F16[1] = F1
    gemm_mma<true, 1024, 1024><<<tcg, 256, SMEM_MMA>>>(
        Af16, W1T, b1, nullptr, nullptr, nullptr, nullptr, nullptr, Hf16);
    gemm_mma<false, 1024, 1024><<<tcg, 256, SMEM_MMA>>>(
        Hf16, W2T, b2, nullptr, z, F16 + SZ, G16 + SZ, nullptr, nullptr);

    for (int k = 2; k < MAXIT; ++k) {
        const int nv   = (k < MHIST) ? k : MHIST;
        const int slot = k % MHIST;
        launch_anderson_mix(nv, slot);   // -> z (xk), Af16
        if (k < MAXIT - 1) {
            gemm_mma<true, 1024, 1024><<<tcg, 256, SMEM_MMA>>>(
                Af16, W1T, b1, nullptr, nullptr, nullptr, nullptr, nullptr, Hf16);
            gemm_mma<false, 1024, 1024><<<tcg, 256, SMEM_MMA>>>(
                Hf16, W2T, b2, nullptr, z,
                F16 + (size_t)slot * SZ, G16 + (size_t)slot * SZ,
                nullptr, nullptr);
        }
    }

    // out = z_star @ W_out + b_out
    gemm_mma<false, 1024, 512><<<dim3(8, 8), 256, SMEM_MMA>>>(
        Af16, WoutT, b_out, out, nullptr, nullptr, nullptr, nullptr, nullptr);
}